// round 1
// baseline (speedup 1.0000x reference)
#include <cuda_runtime.h>
#include <cuda_bf16.h>

// RelativePositionEncoding (AF3-style), GB300 sm_103a
//
// out[i,j,c] = W_pos[d_residue(i,j)][c] + W_tok[d_token(i,j)][c]
//            + same_entity(i,j)*w_ent[c] + W_chain[d_chain(i,j)][c]
//
// Shapes: N=1536 tokens, C_Z=128 channels, F_IN=139 table rows.
// Output = 1536*1536*128 fp32 = 1.208 GB  -> pure HBM-write-bound.
//
// Strategy:
//  - All tables live in shared memory (144 rows x 512B = 72KB):
//    rows [0,66)   = W_pos
//    rows [66,132) = W_tok
//    rows [132,144)= chain2[e][k] = W_chain[k] + e*w_ent   (pre-fused)
//  - One block per output row i; 8 warps stride over j.
//  - One warp per (i,j): lane l handles channels [4l,4l+4) via float4.
//    -> 3x LDS.128 + 8 FADD + 1x STG.128 per pair, fully coalesced 512B bursts.

#define N_TOK 1536
#define CZ 128
#define R_MAX 32
#define S_MAX 2
// table row counts
#define ROWS_TOTAL 144           // 66 pos + 66 tok + 12 fused chain
#define SMEM_BYTES (ROWS_TOTAL * CZ * 4)

__global__ __launch_bounds__(256, 3)
void relpos_kernel(const int* __restrict__ asym,
                   const int* __restrict__ resi,
                   const int* __restrict__ enti,
                   const int* __restrict__ toki,
                   const int* __restrict__ symi,
                   const float* __restrict__ W,
                   float* __restrict__ out)
{
    extern __shared__ float sW[];   // [144][128]
    const int tid = threadIdx.x;

    // ---- Build tables in smem ----
    // W rows: [0,66)=pos, [66,132)=tok, 132=w_ent, [133,139)=chain
    for (int idx = tid; idx < 132 * CZ; idx += blockDim.x)
        sW[idx] = W[idx];
    for (int idx = tid; idx < 12 * CZ; idx += blockDim.x) {
        int row = idx >> 7;          // 0..11
        int c   = idx & (CZ - 1);
        int e   = row / 6;           // 0 or 1 (same-entity flag)
        int k   = row % 6;           // d_chain
        float v = W[(133 + k) * CZ + c];
        if (e) v += W[132 * CZ + c];
        sW[132 * CZ + idx] = v;
    }
    __syncthreads();

    const int i  = blockIdx.x;
    const int ai = asym[i];
    const int ri = resi[i];
    const int ei = enti[i];
    const int ti = toki[i];
    const int si = symi[i];

    const int lane = tid & 31;
    const int warp = tid >> 5;

    const float4* __restrict__ t4 = reinterpret_cast<const float4*>(sW); // row stride 32
    float4* __restrict__ out4 = reinterpret_cast<float4*>(out) + (size_t)i * N_TOK * (CZ / 4);

    for (int j = warp; j < N_TOK; j += 8) {
        const int aj = __ldg(asym + j);
        const int rj = __ldg(resi + j);
        const int ej = __ldg(enti + j);
        const int tj = __ldg(toki + j);
        const int sj = __ldg(symi + j);

        const bool sc  = (ai == aj);
        const int  dr  = sc ? min(max(ri - rj + R_MAX, 0), 2 * R_MAX) : (2 * R_MAX + 1);
        const bool scr = sc && (ri == rj);
        const int  dt  = scr ? min(max(ti - tj + R_MAX, 0), 2 * R_MAX) : (2 * R_MAX + 1);
        const bool se  = (ei == ej);
        const int  dk  = se ? min(max(si - sj + S_MAX, 0), 2 * S_MAX) : (2 * S_MAX + 1);
        const int  dci = (se ? 6 : 0) + dk;   // fused chain-table row

        const float4 a = t4[dr * 32 + lane];
        const float4 b = t4[(66 + dt) * 32 + lane];
        const float4 c = t4[(132 + dci) * 32 + lane];

        float4 r;
        r.x = a.x + b.x + c.x;
        r.y = a.y + b.y + c.y;
        r.z = a.z + b.z + c.z;
        r.w = a.w + b.w + c.w;

        out4[(size_t)j * (CZ / 4) + lane] = r;
    }
}

extern "C" void kernel_launch(void* const* d_in, const int* in_sizes, int n_in,
                              void* d_out, int out_size)
{
    const int*   asym = (const int*)d_in[0];
    const int*   resi = (const int*)d_in[1];
    const int*   enti = (const int*)d_in[2];
    const int*   toki = (const int*)d_in[3];
    const int*   symi = (const int*)d_in[4];
    const float* W    = (const float*)d_in[5];
    float*       out  = (float*)d_out;

    cudaFuncSetAttribute(relpos_kernel,
                         cudaFuncAttributeMaxDynamicSharedMemorySize, SMEM_BYTES);

    relpos_kernel<<<N_TOK, 256, SMEM_BYTES>>>(asym, resi, enti, toki, symi, W, out);
}

// round 2
// speedup vs baseline: 1.7180x; 1.7180x over previous
#include <cuda_runtime.h>
#include <cuda_bf16.h>

// RelativePositionEncoding (AF3-style), GB300 sm_103a — R2
//
// out[i,j,:] = W_pos[dr] + W_tok[dt] + same_ent*w_ent + W_chain[dk]
//
// Identity exploited: dt != 65  =>  (same chain && same residue) => dr == 32.
//                     dt == 65  otherwise.
// So pos+tok always reduces to ONE row of a fused 132-row table:
//   rows [0,66):   F[r] = W_pos[r]  + W_tok[65]   (indexed by dr when !scr)
//   rows [66,132): F[t] = W_pos[32] + W_tok[t]    (indexed by dt when  scr)
// Chain+entity fused into 12 rows:
//   C[e*6+k] = W_chain[k] + e*w_ent
//
// Per block (one output row i):
//   Prologue: build 144-row table (72KB smem) + packed per-j index (3KB smem).
//   Hot loop: per (i,j) pair, warp does
//     1 broadcast LDS (packed idx) + 2 LDS.128 + 4 FADD + 1 STG.128 (streaming).

#define N_TOK 1536
#define CZ 128
#define TBL_FLOATS (144 * CZ)                 // 73728 B
#define IDX_OFF    TBL_FLOATS                  // uint16[1536] lives after table
#define SMEM_BYTES (TBL_FLOATS * 4 + N_TOK * 2)

__global__ __launch_bounds__(256, 3)
void relpos_kernel(const int* __restrict__ asym,
                   const int* __restrict__ resi,
                   const int* __restrict__ enti,
                   const int* __restrict__ toki,
                   const int* __restrict__ symi,
                   const float* __restrict__ W,
                   float* __restrict__ out)
{
    extern __shared__ float sW[];                       // [144][128] fp32
    unsigned short* sIdx = (unsigned short*)(sW + IDX_OFF);  // [1536]

    const int tid = threadIdx.x;
    const int i   = blockIdx.x;

    // ---- Phase 1a: fused pos/tok table (132 rows) ----
    // W rows: [0,66)=pos, [66,132)=tok, 132=w_ent, [133,139)=chain
    #pragma unroll 4
    for (int idx = tid; idx < 132 * CZ; idx += 256) {
        const int row = idx >> 7;
        const int c   = idx & (CZ - 1);
        float v;
        if (row < 66) v = W[row * CZ + c] + W[131 * CZ + c];   // W_pos[row] + W_tok[65]
        else          v = W[32  * CZ + c] + W[row * CZ + c];   // W_pos[32]  + W_tok[row-66]
        sW[idx] = v;
    }
    // ---- Phase 1b: fused chain/entity table (12 rows at offset 132) ----
    for (int idx = tid; idx < 12 * CZ; idx += 256) {
        const int row = idx >> 7;          // 0..11
        const int c   = idx & (CZ - 1);
        const int e   = row / 6;
        const int k   = row % 6;
        float v = W[(133 + k) * CZ + c];
        if (e) v += W[132 * CZ + c];
        sW[132 * CZ + idx] = v;
    }

    // ---- Phase 1c: per-j packed indices for this i ----
    const int ai = asym[i], ri = resi[i], ei = enti[i], ti = toki[i], si = symi[i];
    for (int j = tid; j < N_TOK; j += 256) {
        const int aj = __ldg(asym + j);
        const int rj = __ldg(resi + j);
        const int ej = __ldg(enti + j);
        const int tj = __ldg(toki + j);
        const int sj = __ldg(symi + j);

        const bool sc  = (ai == aj);
        const bool scr = sc && (ri == rj);
        int f;
        if (scr)      f = 66 + min(max(ti - tj + 32, 0), 64);  // token branch
        else if (sc)  f = min(max(ri - rj + 32, 0), 64);       // residue branch
        else          f = 65;                                   // diff chain
        const bool se = (ei == ej);
        const int  dk = se ? min(max(si - sj + 2, 0), 4) : 5;
        const int  dc = (se ? 6 : 0) + dk;                      // 0..11
        sIdx[j] = (unsigned short)(f | (dc << 8));
    }
    __syncthreads();

    // ---- Phase 2: hot loop — 8 warps stride j, unroll x2 ----
    const int lane = tid & 31;
    const int warp = tid >> 5;

    const float4* __restrict__ t4   = reinterpret_cast<const float4*>(sW);          // row stride 32
    const float4* __restrict__ c4   = t4 + 132 * 32;
    float4* __restrict__ out4 = reinterpret_cast<float4*>(out) + (size_t)i * N_TOK * 32;

    #pragma unroll 2
    for (int j = warp * 2; j < N_TOK; j += 16) {
        const unsigned p0 = sIdx[j];
        const unsigned p1 = sIdx[j + 1];

        const float4 a0 = t4[(p0 & 0xFF) * 32 + lane];
        const float4 b0 = c4[(p0 >> 8)   * 32 + lane];
        const float4 a1 = t4[(p1 & 0xFF) * 32 + lane];
        const float4 b1 = c4[(p1 >> 8)   * 32 + lane];

        float4 r0, r1;
        r0.x = a0.x + b0.x; r0.y = a0.y + b0.y; r0.z = a0.z + b0.z; r0.w = a0.w + b0.w;
        r1.x = a1.x + b1.x; r1.y = a1.y + b1.y; r1.z = a1.z + b1.z; r1.w = a1.w + b1.w;

        __stcs(&out4[(size_t)j * 32 + lane],       r0);
        __stcs(&out4[(size_t)(j + 1) * 32 + lane], r1);
    }
}

extern "C" void kernel_launch(void* const* d_in, const int* in_sizes, int n_in,
                              void* d_out, int out_size)
{
    const int*   asym = (const int*)d_in[0];
    const int*   resi = (const int*)d_in[1];
    const int*   enti = (const int*)d_in[2];
    const int*   toki = (const int*)d_in[3];
    const int*   symi = (const int*)d_in[4];
    const float* W    = (const float*)d_in[5];
    float*       out  = (float*)d_out;

    cudaFuncSetAttribute(relpos_kernel,
                         cudaFuncAttributeMaxDynamicSharedMemorySize, SMEM_BYTES);

    relpos_kernel<<<N_TOK, 256, SMEM_BYTES>>>(asym, resi, enti, toki, symi, W, out);
}